// round 14
// baseline (speedup 1.0000x reference)
#include <cuda_runtime.h>
#include <cuda_fp16.h>
#include <math.h>

#define BB     2
#define NPTS   262144
#define KSLOT  9
#define SDIM   64
#define DDIM   64
#define SCALEF 0.125f

#define TILE    128
#define THREADS 128

typedef unsigned long long u64;

// Packed fp32x2 helpers (sm_103a FFMA2 — PTX-only path).
#define FMA_F32X2(d, a, b, c) \
    asm("fma.rn.f32x2 %0, %1, %2, %3;" : "=l"(d) : "l"(a), "l"(b), "l"(c))
#define PACKF2(d, lo, hi) \
    asm("mov.b64 %0, {%1, %2};" : "=l"(d) : "r"(__float_as_uint(lo)), "r"(__float_as_uint(hi)))

__device__ __forceinline__ float2 unpackf2(u64 s) {
    unsigned lo, hi;
    asm("mov.b64 {%0, %1}, %2;" : "=r"(lo), "=r"(hi) : "l"(s));
    return make_float2(__uint_as_float(lo), __uint_as_float(hi));
}

// Precomputed per-batch tiny matrices (written by prep_kernel).
__device__ __align__(16) float g_A[BB][KSLOT][DDIM];   // SCALE * (k @ Wq_w)
__device__ __align__(16) float g_V[BB][KSLOT][DDIM];   // slots_full @ out_w^T
__device__ float g_c[BB][KSLOT];                       // SCALE * (Wq_b . k_j)
__device__ float g_esc[1];                             // exp(density_scale)

// ---------------------------------------------------------------------------
// Prep (fast version): one block per batch, 576 threads = (j,d) pairs.
// Weight matrices staged into shared with coalesced loads first.
// ---------------------------------------------------------------------------
__global__ __launch_bounds__(576)
void prep_kernel(const float* __restrict__ slots,
                 const float* __restrict__ empty_slot,
                 const float* __restrict__ Wq_w,
                 const float* __restrict__ Wq_b,
                 const float* __restrict__ Wk_w,
                 const float* __restrict__ Wk_b,
                 const float* __restrict__ out_w,
                 const float* __restrict__ density_scale) {
    int b   = blockIdx.x;
    int tid = threadIdx.x;        // 0..575
    int j   = tid >> 6;
    int d   = tid & 63;

    __shared__ float sWk[SDIM * DDIM];   // Wk_w  [d][s]
    __shared__ float sWq[DDIM * DDIM];   // Wq_w  [e][d]
    __shared__ float sWo[SDIM * DDIM];   // out_w [d][s]
    __shared__ float sf[KSLOT][SDIM];
    __shared__ float sk[KSLOT][DDIM];

    #pragma unroll
    for (int i = tid; i < SDIM * DDIM; i += 576) {
        sWk[i] = Wk_w[i];
        sWq[i] = Wq_w[i];
        sWo[i] = out_w[i];
    }
    sf[j][d] = (j == 0) ? empty_slot[d]
                        : slots[(b * (KSLOT - 1) + (j - 1)) * SDIM + d];
    __syncthreads();

    float kk = Wk_b[d];
    float vv = 0.f;
    #pragma unroll
    for (int s = 0; s < SDIM; s++) {
        float f = sf[j][s];
        kk = fmaf(f, sWk[d * SDIM + s], kk);
        vv = fmaf(f, sWo[d * SDIM + s], vv);
    }
    sk[j][d] = kk;
    g_V[b][j][d] = vv;
    __syncthreads();

    float aa = 0.f;
    #pragma unroll
    for (int e = 0; e < DDIM; e++)
        aa = fmaf(sk[j][e], sWq[e * DDIM + d], aa);
    g_A[b][j][d] = aa * SCALEF;

    if (tid < KSLOT) {
        float cc = 0.f;
        #pragma unroll
        for (int e = 0; e < DDIM; e++)
            cc = fmaf(Wq_b[e], sk[tid][e], cc);
        g_c[b][tid] = cc * SCALEF;
    }
    if (b == 0 && tid == 0) g_esc[0] = expf(density_scale[0]);
}

// ---------------------------------------------------------------------------
// Main: 128 points / 128-thread block. fp16 x in shared (stride-17 uint2);
// A read as warp-uniform LDG.128 (1 wavefront vs 2 for broadcast LDS.128);
// packed FFMA2 math; phase-2 weights via shfl.
// ---------------------------------------------------------------------------
__global__ __launch_bounds__(THREADS, 6)
void main_kernel(const float* __restrict__ pf,     // [B,N,64]
                 const float* __restrict__ coor,   // [B,N,3]
                 const float* __restrict__ out_b,  // [64]
                 float* __restrict__ xo_out,       // [B,N,64]
                 float* __restrict__ w_out,        // [B,N,9]
                 float* __restrict__ sig_out) {    // [B,N]

    __shared__ uint2 xs[TILE * 17];          // fp16 x: 16 used + 1 pad per point
    __shared__ float ws[TILE * 12];          // softmax weights (w_out write only)

    const int tid  = threadIdx.x;
    const int base = blockIdx.x * TILE;
    const int b    = base / NPTS;            // tiles never straddle batches
    const int g    = base + tid;

    // ---- prefetch coor (independent; hides behind staging) ----
    float cx = coor[g * 3 + 0];
    float cy = coor[g * 3 + 1];
    float cz = coor[g * 3 + 2];

    // ---- stage x tile: coalesced float4 loads, convert to fp16, STS.64 ----
    const float4* src = (const float4*)pf + (size_t)base * 16;
    #pragma unroll
    for (int i = 0; i < 16; i++) {
        int idx = tid + i * THREADS;         // 0..2047
        float4 xv = src[idx];
        __half2 h0 = __float22half2_rn(make_float2(xv.x, xv.y));
        __half2 h1 = __float22half2_rn(make_float2(xv.z, xv.w));
        uint2 u;
        u.x = *reinterpret_cast<unsigned*>(&h0);
        u.y = *reinterpret_cast<unsigned*>(&h1);
        int p = idx >> 4, ev = idx & 15;
        xs[p * 17 + ev] = u;
    }
    __syncthreads();

    // ---- phase 1: logits via packed FFMA2; A via uniform LDG.128 ----
    u64 acc2[KSLOT];
    #pragma unroll
    for (int j = 0; j < KSLOT; j++) acc2[j] = 0ULL;

    const float4* Ag = (const float4*)&g_A[b][0][0];   // [9][16] float4 rows

    #pragma unroll
    for (int qq = 0; qq < 16; qq++) {
        uint2 u = xs[tid * 17 + qq];
        float2 x01 = __half22float2(*reinterpret_cast<__half2*>(&u.x));
        float2 x23 = __half22float2(*reinterpret_cast<__half2*>(&u.y));
        u64 xp0, xp1;
        PACKF2(xp0, x01.x, x01.y);
        PACKF2(xp1, x23.x, x23.y);
        #pragma unroll
        for (int j = 0; j < KSLOT; j++) {
            float4 af = __ldg(&Ag[j * 16 + qq]);       // uniform LDG.128: 1 wf
            ulonglong2 ap = *reinterpret_cast<ulonglong2*>(&af);
            FMA_F32X2(acc2[j], xp0, ap.x, acc2[j]);
            FMA_F32X2(acc2[j], xp1, ap.y, acc2[j]);
        }
    }

    float acc[KSLOT];
    #pragma unroll
    for (int j = 0; j < KSLOT; j++) {
        float2 t = unpackf2(acc2[j]);
        acc[j] = t.x + t.y + __ldg(&g_c[b][j]);
    }

    bool oob = (fabsf(cx) > 1.0f) || (fabsf(cy) > 1.0f) || (fabsf(cz) > 1.0f);
    if (oob) {
        #pragma unroll
        for (int j = 2; j < KSLOT; j++) acc[j] = -INFINITY;
    }

    float m = acc[0];
    #pragma unroll
    for (int j = 1; j < KSLOT; j++) m = fmaxf(m, acc[j]);
    float sum = 0.f;
    float myw[KSLOT];
    #pragma unroll
    for (int j = 0; j < KSLOT; j++) { myw[j] = __expf(acc[j] - m); sum += myw[j]; }
    const float inv = 1.0f / sum;
    #pragma unroll
    for (int j = 0; j < KSLOT; j++) myw[j] *= inv;

    float sig = 0.f;
    #pragma unroll
    for (int j = 1; j < KSLOT; j++)
        sig = fmaf(fmaxf(acc[j], 0.f), myw[j], sig);
    sig_out[g] = sig * g_esc[0];

    // ws only feeds the coalesced w_out write
    *(float4*)&ws[tid * 12 + 0] = make_float4(myw[0], myw[1], myw[2], myw[3]);
    *(float4*)&ws[tid * 12 + 4] = make_float4(myw[4], myw[5], myw[6], myw[7]);
    *(float4*)&ws[tid * 12 + 8] = make_float4(myw[8], 0.f, 0.f, 0.f);

    __syncthreads();

    // ---- coalesced w write: 1152 elems ----
    #pragma unroll
    for (int i = 0; i < (TILE * KSLOT) / THREADS; i++) {   // 9 iters
        int idx = tid + i * THREADS;
        int p = idx / KSLOT, jj = idx - p * KSLOT;
        w_out[(size_t)base * KSLOT + idx] = ws[p * 12 + jj];
    }

    // ---- phase 2: xo. Warp handles its own 32 points; w via shfl.idx. ----
    const int lane = tid & 31;
    const int wrp  = tid >> 5;               // warp id (0..3)
    const int q    = lane & 15;              // d-quad within point
    const int grp  = lane >> 4;              // 0/1: which of the 2 points/iter

    u64 vp0[KSLOT], vp1[KSLOT];
    #pragma unroll
    for (int j = 0; j < KSLOT; j++) {
        ulonglong2 vv = *(const ulonglong2*)&g_V[b][j][q * 4];
        vp0[j] = vv.x; vp1[j] = vv.y;
    }
    ulonglong2 obp = *(const ulonglong2*)&out_b[q * 4];

    #pragma unroll
    for (int it = 0; it < 16; it++) {
        const int srcLane = 2 * it + grp;    // owner lane of this point's weights
        u64 o0 = obp.x, o1 = obp.y;
        #pragma unroll
        for (int j = 0; j < KSLOT; j++) {
            float wj = __shfl_sync(0xffffffffu, myw[j], srcLane);
            u64 wp; PACKF2(wp, wj, wj);
            FMA_F32X2(o0, wp, vp0[j], o0);
            FMA_F32X2(o1, wp, vp1[j], o1);
        }
        const int p = wrp * 32 + 2 * it + grp;   // block-relative point
        ulonglong2 ov; ov.x = o0; ov.y = o1;
        *(ulonglong2*)&xo_out[(size_t)(base + p) * DDIM + q * 4] = ov;  // STG.128
    }
}

// ---------------------------------------------------------------------------
extern "C" void kernel_launch(void* const* d_in, const int* in_sizes, int n_in,
                              void* d_out, int out_size) {
    const float* pf    = (const float*)d_in[0];   // point_feats
    // d_in[1] points_emb: unused (identity stand-in in reference)
    const float* slots = (const float*)d_in[2];
    const float* coor  = (const float*)d_in[3];
    const float* empty = (const float*)d_in[4];
    const float* Wq_w  = (const float*)d_in[5];
    const float* Wq_b  = (const float*)d_in[6];
    const float* Wk_w  = (const float*)d_in[7];
    const float* Wk_b  = (const float*)d_in[8];
    const float* out_w = (const float*)d_in[9];
    const float* ob    = (const float*)d_in[10];
    const float* dsc   = (const float*)d_in[11];
    // d_in[12] Nr: unused

    float* out = (float*)d_out;
    float* xo  = out;                                   // [B,N,64]
    float* w   = xo + (size_t)BB * NPTS * DDIM;         // [B,N,9]
    float* sg  = w  + (size_t)BB * NPTS * KSLOT;        // [B,N]

    prep_kernel<<<BB, 576>>>(slots, empty, Wq_w, Wq_b, Wk_w, Wk_b,
                             out_w, dsc);
    main_kernel<<<(BB * NPTS) / TILE, THREADS>>>(pf, coor, ob, xo, w, sg);
}

// round 15
// speedup vs baseline: 1.0713x; 1.0713x over previous
#include <cuda_runtime.h>
#include <cuda_fp16.h>
#include <math.h>

#define BB     2
#define NPTS   262144
#define KSLOT  9
#define SDIM   64
#define DDIM   64
#define SCALEF 0.125f

#define TILE    128
#define THREADS 64

typedef unsigned long long u64;

// Packed fp32x2 helpers (sm_103a FFMA2 — PTX-only path).
#define FMA_F32X2(d, a, b, c) \
    asm("fma.rn.f32x2 %0, %1, %2, %3;" : "=l"(d) : "l"(a), "l"(b), "l"(c))
#define PACKF2(d, lo, hi) \
    asm("mov.b64 %0, {%1, %2};" : "=l"(d) : "r"(__float_as_uint(lo)), "r"(__float_as_uint(hi)))

__device__ __forceinline__ float2 unpackf2(u64 s) {
    unsigned lo, hi;
    asm("mov.b64 {%0, %1}, %2;" : "=r"(lo), "=r"(hi) : "l"(s));
    return make_float2(__uint_as_float(lo), __uint_as_float(hi));
}

// Precomputed per-batch tiny matrices (written by prep_kernel).
__device__ __align__(16) float g_A[BB][KSLOT][DDIM];   // SCALE * (k @ Wq_w)
__device__ __align__(16) float g_V[BB][KSLOT][DDIM];   // slots_full @ out_w^T
__device__ float g_c[BB][KSLOT];                       // SCALE * (Wq_b . k_j)
__device__ float g_esc[1];                             // exp(density_scale)

// ---------------------------------------------------------------------------
// Prep (fast version): one block per batch, 576 threads = (j,d) pairs.
// ---------------------------------------------------------------------------
__global__ __launch_bounds__(576)
void prep_kernel(const float* __restrict__ slots,
                 const float* __restrict__ empty_slot,
                 const float* __restrict__ Wq_w,
                 const float* __restrict__ Wq_b,
                 const float* __restrict__ Wk_w,
                 const float* __restrict__ Wk_b,
                 const float* __restrict__ out_w,
                 const float* __restrict__ density_scale) {
    int b   = blockIdx.x;
    int tid = threadIdx.x;        // 0..575
    int j   = tid >> 6;
    int d   = tid & 63;

    __shared__ float sWk[SDIM * DDIM];
    __shared__ float sWq[DDIM * DDIM];
    __shared__ float sWo[SDIM * DDIM];
    __shared__ float sf[KSLOT][SDIM];
    __shared__ float sk[KSLOT][DDIM];

    #pragma unroll
    for (int i = tid; i < SDIM * DDIM; i += 576) {
        sWk[i] = Wk_w[i];
        sWq[i] = Wq_w[i];
        sWo[i] = out_w[i];
    }
    sf[j][d] = (j == 0) ? empty_slot[d]
                        : slots[(b * (KSLOT - 1) + (j - 1)) * SDIM + d];
    __syncthreads();

    float kk = Wk_b[d];
    float vv = 0.f;
    #pragma unroll
    for (int s = 0; s < SDIM; s++) {
        float f = sf[j][s];
        kk = fmaf(f, sWk[d * SDIM + s], kk);
        vv = fmaf(f, sWo[d * SDIM + s], vv);
    }
    sk[j][d] = kk;
    g_V[b][j][d] = vv;
    __syncthreads();

    float aa = 0.f;
    #pragma unroll
    for (int e = 0; e < DDIM; e++)
        aa = fmaf(sk[j][e], sWq[e * DDIM + d], aa);
    g_A[b][j][d] = aa * SCALEF;

    if (tid < KSLOT) {
        float cc = 0.f;
        #pragma unroll
        for (int e = 0; e < DDIM; e++)
            cc = fmaf(Wq_b[e], sk[tid][e], cc);
        g_c[b][tid] = cc * SCALEF;
    }
    if (b == 0 && tid == 0) g_esc[0] = expf(density_scale[0]);
}

// ---------------------------------------------------------------------------
// Main: 128 points per 64-thread block (2 points/thread: tid and tid+64).
// Same tile size / grid / barrier structure as the proven R13 kernel; each
// A-matrix LDS.128 now feeds 4 FFMA2 (2 points) instead of 2 -> A L1 traffic
// per point halves.
// ---------------------------------------------------------------------------
__global__ __launch_bounds__(THREADS, 8)
void main_kernel(const float* __restrict__ pf,     // [B,N,64]
                 const float* __restrict__ coor,   // [B,N,3]
                 const float* __restrict__ out_b,  // [64]
                 float* __restrict__ xo_out,       // [B,N,64]
                 float* __restrict__ w_out,        // [B,N,9]
                 float* __restrict__ sig_out) {    // [B,N]

    __shared__ uint2 xs[TILE * 17];          // fp16 x: 16 used + 1 pad per point
    __shared__ float ws[TILE * 12];          // softmax weights
    __shared__ __align__(16) float As[KSLOT * DDIM];
    __shared__ float cs[KSLOT];

    const int tid  = threadIdx.x;            // 0..63
    const int base = blockIdx.x * TILE;
    const int b    = base / NPTS;            // tiles never straddle batches

    // ---- stage A, c ----
    #pragma unroll
    for (int i = tid; i < KSLOT * DDIM; i += THREADS) As[i] = g_A[b][0][i];
    if (tid < KSLOT) cs[tid] = g_c[b][tid];

    // ---- prefetch coor for both points ----
    const int g0 = base + tid;
    const int g1 = base + tid + 64;
    float cxa = coor[g0 * 3 + 0], cya = coor[g0 * 3 + 1], cza = coor[g0 * 3 + 2];
    float cxb = coor[g1 * 3 + 0], cyb = coor[g1 * 3 + 1], czb = coor[g1 * 3 + 2];

    // ---- stage x tile: coalesced float4 loads, convert to fp16, STS.64 ----
    const float4* src = (const float4*)pf + (size_t)base * 16;
    #pragma unroll
    for (int i = 0; i < 32; i++) {
        int idx = tid + i * THREADS;         // 0..2047
        float4 xv = src[idx];
        __half2 h0 = __float22half2_rn(make_float2(xv.x, xv.y));
        __half2 h1 = __float22half2_rn(make_float2(xv.z, xv.w));
        uint2 u;
        u.x = *reinterpret_cast<unsigned*>(&h0);
        u.y = *reinterpret_cast<unsigned*>(&h1);
        int p = idx >> 4, ev = idx & 15;
        xs[p * 17 + ev] = u;
    }
    __syncthreads();

    // ---- phase 1: logits for 2 points, A loads amortized ----
    u64 acc2[2][KSLOT];
    #pragma unroll
    for (int j = 0; j < KSLOT; j++) { acc2[0][j] = 0ULL; acc2[1][j] = 0ULL; }

    #pragma unroll 4
    for (int qq = 0; qq < 16; qq++) {
        uint2 ua = xs[tid * 17 + qq];
        uint2 ub = xs[(tid + 64) * 17 + qq];
        float2 a01 = __half22float2(*reinterpret_cast<__half2*>(&ua.x));
        float2 a23 = __half22float2(*reinterpret_cast<__half2*>(&ua.y));
        float2 b01 = __half22float2(*reinterpret_cast<__half2*>(&ub.x));
        float2 b23 = __half22float2(*reinterpret_cast<__half2*>(&ub.y));
        u64 xa0, xa1, xb0, xb1;
        PACKF2(xa0, a01.x, a01.y);
        PACKF2(xa1, a23.x, a23.y);
        PACKF2(xb0, b01.x, b01.y);
        PACKF2(xb1, b23.x, b23.y);
        #pragma unroll
        for (int j = 0; j < KSLOT; j++) {
            ulonglong2 ap = *(const ulonglong2*)&As[j * DDIM + qq * 4];  // LDS.128
            FMA_F32X2(acc2[0][j], xa0, ap.x, acc2[0][j]);
            FMA_F32X2(acc2[0][j], xa1, ap.y, acc2[0][j]);
            FMA_F32X2(acc2[1][j], xb0, ap.x, acc2[1][j]);
            FMA_F32X2(acc2[1][j], xb1, ap.y, acc2[1][j]);
        }
    }

    const float esc = g_esc[0];
    float myw[2][KSLOT];

    #pragma unroll
    for (int s = 0; s < 2; s++) {
        const int p = tid + s * 64;
        float lg[KSLOT];
        #pragma unroll
        for (int j = 0; j < KSLOT; j++) {
            float2 t = unpackf2(acc2[s][j]);
            lg[j] = t.x + t.y + cs[j];
        }
        float cx = s ? cxb : cxa, cy = s ? cyb : cya, cz = s ? czb : cza;
        bool oob = (fabsf(cx) > 1.0f) || (fabsf(cy) > 1.0f) || (fabsf(cz) > 1.0f);
        if (oob) {
            #pragma unroll
            for (int j = 2; j < KSLOT; j++) lg[j] = -INFINITY;
        }
        float m = lg[0];
        #pragma unroll
        for (int j = 1; j < KSLOT; j++) m = fmaxf(m, lg[j]);
        float sum = 0.f;
        #pragma unroll
        for (int j = 0; j < KSLOT; j++) { myw[s][j] = __expf(lg[j] - m); sum += myw[s][j]; }
        const float inv = 1.0f / sum;
        #pragma unroll
        for (int j = 0; j < KSLOT; j++) myw[s][j] *= inv;

        float sig = 0.f;
        #pragma unroll
        for (int j = 1; j < KSLOT; j++)
            sig = fmaf(fmaxf(lg[j], 0.f), myw[s][j], sig);
        sig_out[base + p] = sig * esc;

        *(float4*)&ws[p * 12 + 0] = make_float4(myw[s][0], myw[s][1], myw[s][2], myw[s][3]);
        *(float4*)&ws[p * 12 + 4] = make_float4(myw[s][4], myw[s][5], myw[s][6], myw[s][7]);
        *(float4*)&ws[p * 12 + 8] = make_float4(myw[s][8], 0.f, 0.f, 0.f);
    }
    __syncthreads();

    // ---- coalesced w write: 1152 elems / 64 threads = 18 iters ----
    #pragma unroll
    for (int i = 0; i < (TILE * KSLOT) / THREADS; i++) {
        int idx = tid + i * THREADS;
        int p = idx / KSLOT, jj = idx - p * KSLOT;
        w_out[(size_t)base * KSLOT + idx] = ws[p * 12 + jj];
    }

    // ---- phase 2: xo. Warp w covers its 64 points; w via shfl.idx. ----
    const int lane = tid & 31;
    const int wrp  = tid >> 5;               // 0..1
    const int q    = lane & 15;              // d-quad within point
    const int grp  = lane >> 4;              // 0/1

    u64 vp0[KSLOT], vp1[KSLOT];
    #pragma unroll
    for (int j = 0; j < KSLOT; j++) {
        ulonglong2 vv = *(const ulonglong2*)&g_V[b][j][q * 4];
        vp0[j] = vv.x; vp1[j] = vv.y;
    }
    ulonglong2 obp = *(const ulonglong2*)&out_b[q * 4];

    #pragma unroll
    for (int s = 0; s < 2; s++) {
        for (int it = 0; it < 16; it++) {
            const int srcLane = 2 * it + grp;        // owner lane within my warp
            u64 o0 = obp.x, o1 = obp.y;
            #pragma unroll
            for (int j = 0; j < KSLOT; j++) {
                float wj = __shfl_sync(0xffffffffu, myw[s][j], srcLane);
                u64 wp; PACKF2(wp, wj, wj);
                FMA_F32X2(o0, wp, vp0[j], o0);
                FMA_F32X2(o1, wp, vp1[j], o1);
            }
            // point owned by lane srcLane of warp wrp, half s:
            const int p = s * 64 + wrp * 32 + 2 * it + grp;
            ulonglong2 ov; ov.x = o0; ov.y = o1;
            *(ulonglong2*)&xo_out[(size_t)(base + p) * DDIM + q * 4] = ov;  // STG.128
        }
    }
}

// ---------------------------------------------------------------------------
extern "C" void kernel_launch(void* const* d_in, const int* in_sizes, int n_in,
                              void* d_out, int out_size) {
    const float* pf    = (const float*)d_in[0];   // point_feats
    // d_in[1] points_emb: unused (identity stand-in in reference)
    const float* slots = (const float*)d_in[2];
    const float* coor  = (const float*)d_in[3];
    const float* empty = (const float*)d_in[4];
    const float* Wq_w  = (const float*)d_in[5];
    const float* Wq_b  = (const float*)d_in[6];
    const float* Wk_w  = (const float*)d_in[7];
    const float* Wk_b  = (const float*)d_in[8];
    const float* out_w = (const float*)d_in[9];
    const float* ob    = (const float*)d_in[10];
    const float* dsc   = (const float*)d_in[11];
    // d_in[12] Nr: unused

    float* out = (float*)d_out;
    float* xo  = out;                                   // [B,N,64]
    float* w   = xo + (size_t)BB * NPTS * DDIM;         // [B,N,9]
    float* sg  = w  + (size_t)BB * NPTS * KSLOT;        // [B,N]

    prep_kernel<<<BB, 576>>>(slots, empty, Wq_w, Wq_b, Wk_w, Wk_b,
                             out_w, dsc);
    main_kernel<<<(BB * NPTS) / TILE, THREADS>>>(pf, coor, ob, xo, w, sg);
}

// round 16
// speedup vs baseline: 1.3484x; 1.2586x over previous
#include <cuda_runtime.h>
#include <cuda_fp16.h>
#include <math.h>

#define BB     2
#define NPTS   262144
#define KSLOT  9
#define SDIM   64
#define DDIM   64
#define SCALEF 0.125f

#define TILE    128
#define THREADS 128

typedef unsigned long long u64;

// Packed fp32x2 helpers (sm_103a FFMA2 — PTX-only path).
#define FMA_F32X2(d, a, b, c) \
    asm("fma.rn.f32x2 %0, %1, %2, %3;" : "=l"(d) : "l"(a), "l"(b), "l"(c))
#define PACKF2(d, lo, hi) \
    asm("mov.b64 %0, {%1, %2};" : "=l"(d) : "r"(__float_as_uint(lo)), "r"(__float_as_uint(hi)))

__device__ __forceinline__ float2 unpackf2(u64 s) {
    unsigned lo, hi;
    asm("mov.b64 {%0, %1}, %2;" : "=r"(lo), "=r"(hi) : "l"(s));
    return make_float2(__uint_as_float(lo), __uint_as_float(hi));
}

// Precomputed per-batch tiny matrices (written by prep_kernel).
__device__ __align__(16) float g_A[BB][KSLOT][DDIM];   // SCALE * (k @ Wq_w)
__device__ __align__(16) float g_V[BB][KSLOT][DDIM];   // slots_full @ out_w^T
__device__ float g_c[BB][KSLOT];                       // SCALE * (Wq_b . k_j)
__device__ float g_esc[1];                             // exp(density_scale)

// ---------------------------------------------------------------------------
// Prep v3: one block per (batch, slot) = 18 blocks, 256 threads.
// Each block stages the weight matrices (block 0 misses to DRAM, the rest hit
// L2) and computes k/V then A/c for its single slot. Critical path = one
// slot's worth of serial work instead of nine.
// ---------------------------------------------------------------------------
__global__ __launch_bounds__(256)
void prep_kernel(const float* __restrict__ slots,
                 const float* __restrict__ empty_slot,
                 const float* __restrict__ Wq_w,
                 const float* __restrict__ Wq_b,
                 const float* __restrict__ Wk_w,
                 const float* __restrict__ Wk_b,
                 const float* __restrict__ out_w,
                 const float* __restrict__ density_scale) {
    const int b   = blockIdx.x / KSLOT;
    const int j   = blockIdx.x - b * KSLOT;
    const int tid = threadIdx.x;          // 0..255

    __shared__ float sWk[SDIM * DDIM];    // Wk_w  [d][s]
    __shared__ float sWq[DDIM * DDIM];    // Wq_w  [e][d]
    __shared__ float sWo[SDIM * DDIM];    // out_w [d][s]
    __shared__ float sf[SDIM];            // this slot's features
    __shared__ float sk[DDIM];            // this slot's k

    // ---- coalesced staging, interleaved for MLP ----
    #pragma unroll
    for (int i = tid; i < SDIM * DDIM; i += 256) {
        sWk[i] = Wk_w[i];
        sWq[i] = Wq_w[i];
        sWo[i] = out_w[i];
    }
    if (tid < SDIM)
        sf[tid] = (j == 0) ? empty_slot[tid]
                           : slots[(b * (KSLOT - 1) + (j - 1)) * SDIM + tid];
    __syncthreads();

    // ---- k and V for this slot (64 active threads, trivial dots) ----
    if (tid < DDIM) {
        const int d = tid;
        float kk = Wk_b[d];
        float vv = 0.f;
        #pragma unroll
        for (int s = 0; s < SDIM; s++) {
            float f = sf[s];
            kk = fmaf(f, sWk[d * SDIM + s], kk);
            vv = fmaf(f, sWo[d * SDIM + s], vv);
        }
        sk[d] = kk;
        g_V[b][j][d] = vv;
    }
    __syncthreads();

    // ---- A and c for this slot ----
    if (tid < DDIM) {
        const int d = tid;
        float aa = 0.f;
        #pragma unroll
        for (int e = 0; e < DDIM; e++)
            aa = fmaf(sk[e], sWq[e * DDIM + d], aa);
        g_A[b][j][d] = aa * SCALEF;
    }
    if (tid == 0) {
        float cc = 0.f;
        #pragma unroll
        for (int e = 0; e < DDIM; e++)
            cc = fmaf(Wq_b[e], sk[e], cc);
        g_c[b][j] = cc * SCALEF;
        if (blockIdx.x == 0) g_esc[0] = expf(density_scale[0]);
    }
}

// ---------------------------------------------------------------------------
// Main (R13 verbatim, measured 51.5us): 128 points / 128-thread block.
// fp16 x in shared (stride-17 uint2), fp32 A in shared, packed FFMA2 math,
// phase-2 weights distributed by shfl (no shared reads).
// ---------------------------------------------------------------------------
__global__ __launch_bounds__(THREADS, 6)
void main_kernel(const float* __restrict__ pf,     // [B,N,64]
                 const float* __restrict__ coor,   // [B,N,3]
                 const float* __restrict__ out_b,  // [64]
                 float* __restrict__ xo_out,       // [B,N,64]
                 float* __restrict__ w_out,        // [B,N,9]
                 float* __restrict__ sig_out) {    // [B,N]

    __shared__ uint2 xs[TILE * 17];          // fp16 x: 16 used + 1 pad per point
    __shared__ float ws[TILE * 12];          // softmax weights (w_out write only)
    __shared__ __align__(16) float As[KSLOT * DDIM];
    __shared__ float cs[KSLOT];

    const int tid  = threadIdx.x;
    const int base = blockIdx.x * TILE;
    const int b    = base / NPTS;            // tiles never straddle batches
    const int g    = base + tid;

    // ---- stage A, c ----
    #pragma unroll
    for (int i = tid; i < KSLOT * DDIM; i += THREADS) As[i] = g_A[b][0][i];
    if (tid < KSLOT) cs[tid] = g_c[b][tid];

    // ---- prefetch coor (independent; hides behind staging) ----
    float cx = coor[g * 3 + 0];
    float cy = coor[g * 3 + 1];
    float cz = coor[g * 3 + 2];

    // ---- stage x tile: coalesced float4 loads, convert to fp16, STS.64 ----
    const float4* src = (const float4*)pf + (size_t)base * 16;
    #pragma unroll
    for (int i = 0; i < 16; i++) {
        int idx = tid + i * THREADS;         // 0..2047
        float4 xv = src[idx];
        __half2 h0 = __float22half2_rn(make_float2(xv.x, xv.y));
        __half2 h1 = __float22half2_rn(make_float2(xv.z, xv.w));
        uint2 u;
        u.x = *reinterpret_cast<unsigned*>(&h0);
        u.y = *reinterpret_cast<unsigned*>(&h1);
        int p = idx >> 4, ev = idx & 15;
        xs[p * 17 + ev] = u;
    }
    __syncthreads();

    // ---- phase 1: logits via packed FFMA2 ----
    u64 acc2[KSLOT];
    #pragma unroll
    for (int j = 0; j < KSLOT; j++) acc2[j] = 0ULL;

    #pragma unroll
    for (int qq = 0; qq < 16; qq++) {
        uint2 u = xs[tid * 17 + qq];
        float2 x01 = __half22float2(*reinterpret_cast<__half2*>(&u.x));
        float2 x23 = __half22float2(*reinterpret_cast<__half2*>(&u.y));
        u64 xp0, xp1;
        PACKF2(xp0, x01.x, x01.y);
        PACKF2(xp1, x23.x, x23.y);
        #pragma unroll
        for (int j = 0; j < KSLOT; j++) {
            ulonglong2 ap = *(const ulonglong2*)&As[j * DDIM + qq * 4];  // LDS.128
            FMA_F32X2(acc2[j], xp0, ap.x, acc2[j]);
            FMA_F32X2(acc2[j], xp1, ap.y, acc2[j]);
        }
    }

    float acc[KSLOT];
    #pragma unroll
    for (int j = 0; j < KSLOT; j++) {
        float2 t = unpackf2(acc2[j]);
        acc[j] = t.x + t.y + cs[j];
    }

    bool oob = (fabsf(cx) > 1.0f) || (fabsf(cy) > 1.0f) || (fabsf(cz) > 1.0f);
    if (oob) {
        #pragma unroll
        for (int j = 2; j < KSLOT; j++) acc[j] = -INFINITY;
    }

    float m = acc[0];
    #pragma unroll
    for (int j = 1; j < KSLOT; j++) m = fmaxf(m, acc[j]);
    float sum = 0.f;
    float myw[KSLOT];
    #pragma unroll
    for (int j = 0; j < KSLOT; j++) { myw[j] = __expf(acc[j] - m); sum += myw[j]; }
    const float inv = 1.0f / sum;
    #pragma unroll
    for (int j = 0; j < KSLOT; j++) myw[j] *= inv;

    float sig = 0.f;
    #pragma unroll
    for (int j = 1; j < KSLOT; j++)
        sig = fmaf(fmaxf(acc[j], 0.f), myw[j], sig);
    sig_out[g] = sig * g_esc[0];

    // ws only feeds the coalesced w_out write
    *(float4*)&ws[tid * 12 + 0] = make_float4(myw[0], myw[1], myw[2], myw[3]);
    *(float4*)&ws[tid * 12 + 4] = make_float4(myw[4], myw[5], myw[6], myw[7]);
    *(float4*)&ws[tid * 12 + 8] = make_float4(myw[8], 0.f, 0.f, 0.f);

    __syncthreads();

    // ---- coalesced w write: 1152 elems ----
    #pragma unroll
    for (int i = 0; i < (TILE * KSLOT) / THREADS; i++) {   // 9 iters
        int idx = tid + i * THREADS;
        int p = idx / KSLOT, jj = idx - p * KSLOT;
        w_out[(size_t)base * KSLOT + idx] = ws[p * 12 + jj];
    }

    // ---- phase 2: xo. Warp handles its own 32 points; w via shfl.idx. ----
    const int lane = tid & 31;
    const int wrp  = tid >> 5;               // warp id (0..3)
    const int q    = lane & 15;              // d-quad within point
    const int grp  = lane >> 4;              // 0/1: which of the 2 points/iter

    u64 vp0[KSLOT], vp1[KSLOT];
    #pragma unroll
    for (int j = 0; j < KSLOT; j++) {
        ulonglong2 vv = *(const ulonglong2*)&g_V[b][j][q * 4];
        vp0[j] = vv.x; vp1[j] = vv.y;
    }
    ulonglong2 obp = *(const ulonglong2*)&out_b[q * 4];

    #pragma unroll
    for (int it = 0; it < 16; it++) {
        const int srcLane = 2 * it + grp;    // owner lane of this point's weights
        u64 o0 = obp.x, o1 = obp.y;
        #pragma unroll
        for (int j = 0; j < KSLOT; j++) {
            float wj = __shfl_sync(0xffffffffu, myw[j], srcLane);
            u64 wp; PACKF2(wp, wj, wj);
            FMA_F32X2(o0, wp, vp0[j], o0);
            FMA_F32X2(o1, wp, vp1[j], o1);
        }
        const int p = wrp * 32 + 2 * it + grp;   // block-relative point
        ulonglong2 ov; ov.x = o0; ov.y = o1;
        *(ulonglong2*)&xo_out[(size_t)(base + p) * DDIM + q * 4] = ov;  // STG.128
    }
}

// ---------------------------------------------------------------------------
extern "C" void kernel_launch(void* const* d_in, const int* in_sizes, int n_in,
                              void* d_out, int out_size) {
    const float* pf    = (const float*)d_in[0];   // point_feats
    // d_in[1] points_emb: unused (identity stand-in in reference)
    const float* slots = (const float*)d_in[2];
    const float* coor  = (const float*)d_in[3];
    const float* empty = (const float*)d_in[4];
    const float* Wq_w  = (const float*)d_in[5];
    const float* Wq_b  = (const float*)d_in[6];
    const float* Wk_w  = (const float*)d_in[7];
    const float* Wk_b  = (const float*)d_in[8];
    const float* out_w = (const float*)d_in[9];
    const float* ob    = (const float*)d_in[10];
    const float* dsc   = (const float*)d_in[11];
    // d_in[12] Nr: unused

    float* out = (float*)d_out;
    float* xo  = out;                                   // [B,N,64]
    float* w   = xo + (size_t)BB * NPTS * DDIM;         // [B,N,9]
    float* sg  = w  + (size_t)BB * NPTS * KSLOT;        // [B,N]

    prep_kernel<<<BB * KSLOT, 256>>>(slots, empty, Wq_w, Wq_b, Wk_w, Wk_b,
                                     out_w, dsc);
    main_kernel<<<(BB * NPTS) / TILE, THREADS>>>(pf, coor, ob, xo, w, sg);
}